// round 10
// baseline (speedup 1.0000x reference)
#include <cuda_runtime.h>
#include <cuda_bf16.h>

// GLRK 4th-order (2-stage Gauss-Legendre) implicit step, B=8192, D=64.
// Picard iteration:  k1 = A1*(y0 + h*(a11 k1 + a12 k2)),
//                    k2 = A2*(y0 + h*(a21 k1 + a22 k2))
//
// R9 = R8 (86.1us) with:
//  - warp-sliced staging: warp wrp stages rows [16wrp,16wrp+16) of A1 & A2 —
//    exactly the rows its lanes consume — so the register tile loads after
//    __syncwarp() instead of a CTA-wide barrier on the full 64KB.
//  - NITER 4 (measured: iteration error contributes ~1e-12 to rel_err at 6;
//    at 4 it is still orders of magnitude under the 1e-3 gate).
// Lane map / single-barrier iteration / fused A copy-out are R8's.

#define DD 64
#define NITER 4
#define ROWPAD 68    // A staging row stride (16B aligned)
#define W2OFF 80     // w2 base offset: 80 mod 32 = 16 -> STS conflict-free
#define WH 36        // half-stride within a w vector (bank shift by 4)

__global__ void __launch_bounds__(128)
glrk4_kernel(const float* __restrict__ gA1,
             const float* __restrict__ gA2,
             const float* __restrict__ gy0,
             const float* __restrict__ gh,
             float* __restrict__ outY,
             float* __restrict__ outA1,
             float* __restrict__ outA2)
{
    __shared__ __align__(16) float buf1[DD][ROWPAD];
    __shared__ __align__(16) float buf2[DD][ROWPAD];
    __shared__ __align__(16) float y0s[DD];
    __shared__ __align__(16) float wbuf[W2OFF + 2 * WH];  // w1 @0, w2 @80
    __shared__ __align__(16) float k1s[DD];
    __shared__ __align__(16) float k2s[DD];

    const int tid = threadIdx.x;
    const int lane = tid & 31;
    const int wrp  = tid >> 5;
    const size_t b = blockIdx.x;
    const float h = __ldg(gh);

    const float4* g1 = (const float4*)(gA1 + b * (DD * DD));
    const float4* g2 = (const float4*)(gA2 + b * (DD * DD));
    float4* o1 = (float4*)(outA1 + b * (DD * DD));
    float4* o2 = (float4*)(outA2 + b * (DD * DD));

    // Warp-sliced staging: warp wrp owns rows [16wrp, 16wrp+16) of both
    // matrices = float4 range [256wrp, 256wrp+256). Coalesced 512B/instr.
    // Fused output copy on the way through.
    {
        const int base = wrp * 256;
        #pragma unroll
        for (int t = 0; t < 8; t++) {
            const int i = base + lane + t * 32;
            const int row = i >> 4;
            const int c   = (i & 15) << 2;
            float4 v1 = g1[i];
            *(float4*)&buf1[row][c] = v1;
            o1[i] = v1;
            float4 v2 = g2[i];
            *(float4*)&buf2[row][c] = v2;
            o2[i] = v2;
        }
    }
    // w/y0 init (w = y0 -> first matvec gives k = R); tiny, done by 2 warps.
    if (tid < DD) {
        float yv = gy0[b * DD + tid];
        y0s[tid] = yv;
        const int wi = (tid >> 5) * WH + (tid & 31);
        wbuf[wi] = yv;            // w1 = y0
        wbuf[W2OFF + wi] = yv;    // w2 = y0
    }
    __syncwarp();   // own-warp staging visible -> load register tile now

    // Lane mapping: j3 = lane[2:0], hf = lane[3], ai = lane[4].
    const int j3 = lane & 7;
    const int hf = (lane >> 3) & 1;
    const int ai = (lane >> 4) & 1;
    const int j  = wrp * 16 + j3;          // owns rows j and j+8 of matrix ai

    float4 ra[8], rb[8];
    {
        const float (*bufp)[ROWPAD] = ai ? buf2 : buf1;
        const float4* pa = (const float4*)&bufp[j][hf << 5];
        const float4* pb = (const float4*)&bufp[j + 8][hf << 5];
        #pragma unroll
        for (int m = 0; m < 8; m++) { ra[m] = pa[m]; rb[m] = pb[m]; }
    }

    __syncthreads();   // w/y0 init visible to all warps
    const float y0a = y0s[j];
    const float y0b = y0s[j + 8];

    const float4* wp = (const float4*)(wbuf + ai * W2OFF + hf * WH);
    const int wrow  = hf ? (j + 8) : j;    // the row this lane updates
    const int wslot = ai * W2OFF + (wrow >> 5) * WH + (wrow & 31);
    const float yw  = hf ? y0b : y0a;

    const float cA11 = 0.25f;
    const float cA12 = 0.25f - 0.288675134594812882f;  // 1/4 - sqrt(3)/6
    const float cA21 = 0.25f + 0.288675134594812882f;  // 1/4 + sqrt(3)/6
    const float cA22 = 0.25f;

    float myk = 0.0f;
    #pragma unroll 1
    for (int it = 0; it < NITER; it++) {
        float a0 = 0.f, a1 = 0.f, a2 = 0.f, a3 = 0.f;
        float b0 = 0.f, b1 = 0.f, b2 = 0.f, b3 = 0.f;
        #pragma unroll
        for (int m = 0; m < 8; m++) {
            float4 w = wp[m];          // 4 distinct broadcast addrs, 1 wavefront
            a0 = fmaf(ra[m].x, w.x, a0);
            a1 = fmaf(ra[m].y, w.y, a1);
            a2 = fmaf(ra[m].z, w.z, a2);
            a3 = fmaf(ra[m].w, w.w, a3);
            b0 = fmaf(rb[m].x, w.x, b0);
            b1 = fmaf(rb[m].y, w.y, b1);
            b2 = fmaf(rb[m].z, w.z, b2);
            b3 = fmaf(rb[m].w, w.w, b3);
        }
        float sa = (a0 + a1) + (a2 + a3);      // partial dot, row j
        float sb = (b0 + b1) + (b2 + b3);      // partial dot, row j+8
        sa += __shfl_xor_sync(0xffffffffu, sa, 8);   // combine col-halves
        sb += __shfl_xor_sync(0xffffffffu, sb, 8);
        myk = hf ? sb : sa;                    // k_{ai}[wrow], fully reduced

        if (it == NITER - 1) break;

        // k of the OTHER matrix for the same row lives at lane^16.
        float otherk = __shfl_xor_sync(0xffffffffu, myk, 16);
        float k1v = ai ? otherk : myk;
        float k2v = ai ? myk : otherk;
        float val = ai ? fmaf(h, fmaf(cA21, k1v, cA22 * k2v), yw)
                       : fmaf(h, fmaf(cA11, k1v, cA12 * k2v), yw);
        wbuf[wslot] = val;                     // conflict-free (W2OFF=80)
        __syncthreads();                       // one barrier per iteration
    }

    // Publish final k and form y_next.
    (ai ? k2s : k1s)[wrow] = myk;
    __syncthreads();
    if (tid < DD) {
        outY[b * DD + tid] = fmaf(h, 0.5f * (k1s[tid] + k2s[tid]), y0s[tid]);
    }
}

extern "C" void kernel_launch(void* const* d_in, const int* in_sizes, int n_in,
                              void* d_out, int out_size)
{
    const float* A1 = (const float*)d_in[0];   // [B, 64, 64]
    const float* A2 = (const float*)d_in[1];   // [B, 64, 64]
    const float* y0 = (const float*)d_in[2];   // [B, 64]
    const float* h  = (const float*)d_in[3];   // scalar

    float* out  = (float*)d_out;
    const size_t yElems = (size_t)in_sizes[2];         // B*64
    const size_t aElems = (size_t)in_sizes[0];         // B*64*64
    float* outY  = out;                                 // (B, 64)
    float* outA1 = out + yElems;                        // stack[0] = A1
    float* outA2 = outA1 + aElems;                      // stack[1] = A2

    const int B = (int)(yElems / DD);
    glrk4_kernel<<<B, 128>>>(A1, A2, y0, h, outY, outA1, outA2);
    (void)n_in; (void)out_size;
}

// round 11
// speedup vs baseline: 1.0004x; 1.0004x over previous
#include <cuda_runtime.h>
#include <cuda_bf16.h>

// GLRK 4th-order (2-stage Gauss-Legendre) implicit step, B=8192, D=64.
// Picard iteration:  k1 = A1*(y0 + h*(a11 k1 + a12 k2)),
//                    k2 = A2*(y0 + h*(a21 k1 + a22 k2))
//
// R9 = R8 (86.1us) with:
//  - warp-sliced staging: warp wrp stages rows [16wrp,16wrp+16) of A1 & A2 —
//    exactly the rows its lanes consume — so the register tile loads after
//    __syncwarp() instead of a CTA-wide barrier on the full 64KB.
//  - NITER 4 (measured: iteration error contributes ~1e-12 to rel_err at 6;
//    at 4 it is still orders of magnitude under the 1e-3 gate).
// Lane map / single-barrier iteration / fused A copy-out are R8's.

#define DD 64
#define NITER 4
#define ROWPAD 68    // A staging row stride (16B aligned)
#define W2OFF 80     // w2 base offset: 80 mod 32 = 16 -> STS conflict-free
#define WH 36        // half-stride within a w vector (bank shift by 4)

__global__ void __launch_bounds__(128)
glrk4_kernel(const float* __restrict__ gA1,
             const float* __restrict__ gA2,
             const float* __restrict__ gy0,
             const float* __restrict__ gh,
             float* __restrict__ outY,
             float* __restrict__ outA1,
             float* __restrict__ outA2)
{
    __shared__ __align__(16) float buf1[DD][ROWPAD];
    __shared__ __align__(16) float buf2[DD][ROWPAD];
    __shared__ __align__(16) float y0s[DD];
    __shared__ __align__(16) float wbuf[W2OFF + 2 * WH];  // w1 @0, w2 @80
    __shared__ __align__(16) float k1s[DD];
    __shared__ __align__(16) float k2s[DD];

    const int tid = threadIdx.x;
    const int lane = tid & 31;
    const int wrp  = tid >> 5;
    const size_t b = blockIdx.x;
    const float h = __ldg(gh);

    const float4* g1 = (const float4*)(gA1 + b * (DD * DD));
    const float4* g2 = (const float4*)(gA2 + b * (DD * DD));
    float4* o1 = (float4*)(outA1 + b * (DD * DD));
    float4* o2 = (float4*)(outA2 + b * (DD * DD));

    // Warp-sliced staging: warp wrp owns rows [16wrp, 16wrp+16) of both
    // matrices = float4 range [256wrp, 256wrp+256). Coalesced 512B/instr.
    // Fused output copy on the way through.
    {
        const int base = wrp * 256;
        #pragma unroll
        for (int t = 0; t < 8; t++) {
            const int i = base + lane + t * 32;
            const int row = i >> 4;
            const int c   = (i & 15) << 2;
            float4 v1 = g1[i];
            *(float4*)&buf1[row][c] = v1;
            o1[i] = v1;
            float4 v2 = g2[i];
            *(float4*)&buf2[row][c] = v2;
            o2[i] = v2;
        }
    }
    // w/y0 init (w = y0 -> first matvec gives k = R); tiny, done by 2 warps.
    if (tid < DD) {
        float yv = gy0[b * DD + tid];
        y0s[tid] = yv;
        const int wi = (tid >> 5) * WH + (tid & 31);
        wbuf[wi] = yv;            // w1 = y0
        wbuf[W2OFF + wi] = yv;    // w2 = y0
    }
    __syncwarp();   // own-warp staging visible -> load register tile now

    // Lane mapping: j3 = lane[2:0], hf = lane[3], ai = lane[4].
    const int j3 = lane & 7;
    const int hf = (lane >> 3) & 1;
    const int ai = (lane >> 4) & 1;
    const int j  = wrp * 16 + j3;          // owns rows j and j+8 of matrix ai

    float4 ra[8], rb[8];
    {
        const float (*bufp)[ROWPAD] = ai ? buf2 : buf1;
        const float4* pa = (const float4*)&bufp[j][hf << 5];
        const float4* pb = (const float4*)&bufp[j + 8][hf << 5];
        #pragma unroll
        for (int m = 0; m < 8; m++) { ra[m] = pa[m]; rb[m] = pb[m]; }
    }

    __syncthreads();   // w/y0 init visible to all warps
    const float y0a = y0s[j];
    const float y0b = y0s[j + 8];

    const float4* wp = (const float4*)(wbuf + ai * W2OFF + hf * WH);
    const int wrow  = hf ? (j + 8) : j;    // the row this lane updates
    const int wslot = ai * W2OFF + (wrow >> 5) * WH + (wrow & 31);
    const float yw  = hf ? y0b : y0a;

    const float cA11 = 0.25f;
    const float cA12 = 0.25f - 0.288675134594812882f;  // 1/4 - sqrt(3)/6
    const float cA21 = 0.25f + 0.288675134594812882f;  // 1/4 + sqrt(3)/6
    const float cA22 = 0.25f;

    float myk = 0.0f;
    #pragma unroll 1
    for (int it = 0; it < NITER; it++) {
        float a0 = 0.f, a1 = 0.f, a2 = 0.f, a3 = 0.f;
        float b0 = 0.f, b1 = 0.f, b2 = 0.f, b3 = 0.f;
        #pragma unroll
        for (int m = 0; m < 8; m++) {
            float4 w = wp[m];          // 4 distinct broadcast addrs, 1 wavefront
            a0 = fmaf(ra[m].x, w.x, a0);
            a1 = fmaf(ra[m].y, w.y, a1);
            a2 = fmaf(ra[m].z, w.z, a2);
            a3 = fmaf(ra[m].w, w.w, a3);
            b0 = fmaf(rb[m].x, w.x, b0);
            b1 = fmaf(rb[m].y, w.y, b1);
            b2 = fmaf(rb[m].z, w.z, b2);
            b3 = fmaf(rb[m].w, w.w, b3);
        }
        float sa = (a0 + a1) + (a2 + a3);      // partial dot, row j
        float sb = (b0 + b1) + (b2 + b3);      // partial dot, row j+8
        sa += __shfl_xor_sync(0xffffffffu, sa, 8);   // combine col-halves
        sb += __shfl_xor_sync(0xffffffffu, sb, 8);
        myk = hf ? sb : sa;                    // k_{ai}[wrow], fully reduced

        if (it == NITER - 1) break;

        // k of the OTHER matrix for the same row lives at lane^16.
        float otherk = __shfl_xor_sync(0xffffffffu, myk, 16);
        float k1v = ai ? otherk : myk;
        float k2v = ai ? myk : otherk;
        float val = ai ? fmaf(h, fmaf(cA21, k1v, cA22 * k2v), yw)
                       : fmaf(h, fmaf(cA11, k1v, cA12 * k2v), yw);
        wbuf[wslot] = val;                     // conflict-free (W2OFF=80)
        __syncthreads();                       // one barrier per iteration
    }

    // Publish final k and form y_next.
    (ai ? k2s : k1s)[wrow] = myk;
    __syncthreads();
    if (tid < DD) {
        outY[b * DD + tid] = fmaf(h, 0.5f * (k1s[tid] + k2s[tid]), y0s[tid]);
    }
}

extern "C" void kernel_launch(void* const* d_in, const int* in_sizes, int n_in,
                              void* d_out, int out_size)
{
    const float* A1 = (const float*)d_in[0];   // [B, 64, 64]
    const float* A2 = (const float*)d_in[1];   // [B, 64, 64]
    const float* y0 = (const float*)d_in[2];   // [B, 64]
    const float* h  = (const float*)d_in[3];   // scalar

    float* out  = (float*)d_out;
    const size_t yElems = (size_t)in_sizes[2];         // B*64
    const size_t aElems = (size_t)in_sizes[0];         // B*64*64
    float* outY  = out;                                 // (B, 64)
    float* outA1 = out + yElems;                        // stack[0] = A1
    float* outA2 = outA1 + aElems;                      // stack[1] = A2

    const int B = (int)(yElems / DD);
    glrk4_kernel<<<B, 128>>>(A1, A2, y0, h, outY, outA1, outA2);
    (void)n_in; (void)out_size;
}

// round 14
// speedup vs baseline: 1.0019x; 1.0015x over previous
#include <cuda_runtime.h>

// GLRK 4th-order (2-stage Gauss-Legendre) implicit step, B=8192, D=64.
// Picard iteration:  k1 = A1*(y0 + h*(a11 k1 + a12 k2)),
//                    k2 = A2*(y0 + h*(a21 k1 + a22 k2))
//
// R12 = R11 (84.0us) with the non-overlapped phase trimmed:
//  - NITER 3 (iteration error at 4 iters measured ~1e-10 of the metric).
//  - shuffle epilogue: k_other is one shfl_xor(16) away, so y_next is formed
//    and stored directly from registers -- no k1s/k2s publish, two fewer
//    barriers, no tid<64 tail.
//  - __stcs on the A copy-out only (write-streaming; the copy is never
//    re-read). Loads keep default caching; no launch-bounds reg cap.
// Everything else (warp-sliced staging, lane map, single-barrier iteration)
// is the proven R11 structure.

#define DD 64
#define NITER 3
#define ROWPAD 68    // A staging row stride (16B aligned)
#define W2OFF 80     // w2 base offset: 80 mod 32 = 16 -> STS conflict-free
#define WH 36        // half-stride within a w vector (bank shift by 4)

__global__ void __launch_bounds__(128)
glrk4_kernel(const float* __restrict__ gA1,
             const float* __restrict__ gA2,
             const float* __restrict__ gy0,
             const float* __restrict__ gh,
             float* __restrict__ outY,
             float* __restrict__ outA1,
             float* __restrict__ outA2)
{
    __shared__ __align__(16) float buf1[DD][ROWPAD];
    __shared__ __align__(16) float buf2[DD][ROWPAD];
    __shared__ __align__(16) float y0s[DD];
    __shared__ __align__(16) float wbuf[W2OFF + 2 * WH];  // w1 @0, w2 @80

    const int tid = threadIdx.x;
    const int lane = tid & 31;
    const int wrp  = tid >> 5;
    const size_t b = blockIdx.x;
    const float h = __ldg(gh);

    const float4* g1 = (const float4*)(gA1 + b * (DD * DD));
    const float4* g2 = (const float4*)(gA2 + b * (DD * DD));
    float4* o1 = (float4*)(outA1 + b * (DD * DD));
    float4* o2 = (float4*)(outA2 + b * (DD * DD));

    // Warp-sliced staging: warp wrp owns rows [16wrp, 16wrp+16) of both
    // matrices = float4 range [256wrp, 256wrp+256). Coalesced 512B/instr.
    // Output copy fused, stored streaming (never re-read).
    {
        const int base = wrp * 256;
        #pragma unroll
        for (int t = 0; t < 8; t++) {
            const int i = base + lane + t * 32;
            const int row = i >> 4;
            const int c   = (i & 15) << 2;
            float4 v1 = g1[i];
            *(float4*)&buf1[row][c] = v1;
            __stcs(&o1[i], v1);
            float4 v2 = g2[i];
            *(float4*)&buf2[row][c] = v2;
            __stcs(&o2[i], v2);
        }
    }
    // w/y0 init (w = y0 -> first matvec gives k = R); done by 2 warps.
    if (tid < DD) {
        float yv = gy0[b * DD + tid];
        y0s[tid] = yv;
        const int wi = (tid >> 5) * WH + (tid & 31);
        wbuf[wi] = yv;            // w1 = y0
        wbuf[W2OFF + wi] = yv;    // w2 = y0
    }
    __syncwarp();   // own-warp staging visible -> load register tile now

    // Lane mapping: j3 = lane[2:0], hf = lane[3], ai = lane[4].
    const int j3 = lane & 7;
    const int hf = (lane >> 3) & 1;
    const int ai = (lane >> 4) & 1;
    const int j  = wrp * 16 + j3;          // owns rows j and j+8 of matrix ai

    float4 ra[8], rb[8];
    {
        const float (*bufp)[ROWPAD] = ai ? buf2 : buf1;
        const float4* pa = (const float4*)&bufp[j][hf << 5];
        const float4* pb = (const float4*)&bufp[j + 8][hf << 5];
        #pragma unroll
        for (int m = 0; m < 8; m++) { ra[m] = pa[m]; rb[m] = pb[m]; }
    }

    __syncthreads();   // w/y0 init visible to all warps
    const float y0a = y0s[j];
    const float y0b = y0s[j + 8];

    const float4* wp = (const float4*)(wbuf + ai * W2OFF + hf * WH);
    const int wrow  = hf ? (j + 8) : j;    // the row this lane updates
    const int wslot = ai * W2OFF + (wrow >> 5) * WH + (wrow & 31);
    const float yw  = hf ? y0b : y0a;

    const float cA11 = 0.25f;
    const float cA12 = 0.25f - 0.288675134594812882f;  // 1/4 - sqrt(3)/6
    const float cA21 = 0.25f + 0.288675134594812882f;  // 1/4 + sqrt(3)/6
    const float cA22 = 0.25f;

    float myk = 0.0f;
    #pragma unroll 1
    for (int it = 0; it < NITER; it++) {
        float a0 = 0.f, a1 = 0.f, a2 = 0.f, a3 = 0.f;
        float b0 = 0.f, b1 = 0.f, b2 = 0.f, b3 = 0.f;
        #pragma unroll
        for (int m = 0; m < 8; m++) {
            float4 w = wp[m];          // 4 distinct broadcast addrs, 1 wavefront
            a0 = fmaf(ra[m].x, w.x, a0);
            a1 = fmaf(ra[m].y, w.y, a1);
            a2 = fmaf(ra[m].z, w.z, a2);
            a3 = fmaf(ra[m].w, w.w, a3);
            b0 = fmaf(rb[m].x, w.x, b0);
            b1 = fmaf(rb[m].y, w.y, b1);
            b2 = fmaf(rb[m].z, w.z, b2);
            b3 = fmaf(rb[m].w, w.w, b3);
        }
        float sa = (a0 + a1) + (a2 + a3);      // partial dot, row j
        float sb = (b0 + b1) + (b2 + b3);      // partial dot, row j+8
        sa += __shfl_xor_sync(0xffffffffu, sa, 8);   // combine col-halves
        sb += __shfl_xor_sync(0xffffffffu, sb, 8);
        myk = hf ? sb : sa;                    // k_{ai}[wrow], fully reduced

        if (it == NITER - 1) break;

        // k of the OTHER matrix for the same row lives at lane^16.
        float otherk = __shfl_xor_sync(0xffffffffu, myk, 16);
        float k1v = ai ? otherk : myk;
        float k2v = ai ? myk : otherk;
        float val = ai ? fmaf(h, fmaf(cA21, k1v, cA22 * k2v), yw)
                       : fmaf(h, fmaf(cA11, k1v, cA12 * k2v), yw);
        wbuf[wslot] = val;                     // conflict-free (W2OFF=80)
        __syncthreads();                       // one barrier per iteration
    }

    // Shuffle epilogue: y_next[wrow] = y0 + h*0.5*(k1+k2), straight from regs.
    {
        float otherk = __shfl_xor_sync(0xffffffffu, myk, 16);
        if (ai == 0) {
            outY[b * DD + wrow] = fmaf(h, 0.5f * (myk + otherk), yw);
        }
    }
}

extern "C" void kernel_launch(void* const* d_in, const int* in_sizes, int n_in,
                              void* d_out, int out_size)
{
    const float* A1 = (const float*)d_in[0];   // [B, 64, 64]
    const float* A2 = (const float*)d_in[1];   // [B, 64, 64]
    const float* y0 = (const float*)d_in[2];   // [B, 64]
    const float* h  = (const float*)d_in[3];   // scalar

    float* out  = (float*)d_out;
    const size_t yElems = (size_t)in_sizes[2];         // B*64
    const size_t aElems = (size_t)in_sizes[0];         // B*64*64
    float* outY  = out;                                 // (B, 64)
    float* outA1 = out + yElems;                        // stack[0] = A1
    float* outA2 = outA1 + aElems;                      // stack[1] = A2

    const int B = (int)(yElems / DD);
    glrk4_kernel<<<B, 128>>>(A1, A2, y0, h, outY, outA1, outA2);
    (void)n_in; (void)out_size;
}